// round 4
// baseline (speedup 1.0000x reference)
#include <cuda_runtime.h>
#include <cuda_bf16.h>

// YOLO loss: N=64, S=128, B=2.
// input (N,S,S,10) fp32, target (N,S,S,5) fp32 -> 5 fp32 scalars.
// Single fused kernel, 4 cells/thread, 128-thread blocks, big reg budget
// so all 20 loads per thread are front-batched (MLP ~20).

#define NCELLS (64 * 128 * 128)
#define THREADS 128
#define NWARPS (THREADS / 32)
#define NPAIRS (NCELLS / 2)              // 524288 pair-groups (2 cells each)
#define BLOCKS (NPAIRS / (THREADS * 2))  // 2048 blocks, 2 pair-groups/thread

// zero-initialized at module load; last block resets them each replay
__device__ float g_acc[6];   // 0:S_noobj 1:S_xy 2:S_wh 3:S_obj 4:S_nresp 5:m
__device__ unsigned int g_count;

__device__ __forceinline__ float softplus_fast(float x) {
    return fmaxf(x, 0.0f) + __logf(1.0f + __expf(-fabsf(x)));
}
__device__ __forceinline__ float sigmoid_fast(float x) {
    return __fdividef(1.0f, 1.0f + __expf(-x));
}

// Branchless single-cell processing (float-mask weighted accumulation).
__device__ __forceinline__ void process_cell(
    float l0, float x0, float y0, float w0, float h0,
    float l1, float x1, float y1, float w1, float h1,
    float tconf, float tx, float ty, float tw, float th,
    float& s_noobj, float& s_xy, float& s_wh,
    float& s_obj, float& s_nresp, float& s_m)
{
    float obj = (tconf > 0.0f) ? 1.0f : 0.0f;
    float noobj = 1.0f - obj;

    float bce0_0 = softplus_fast(l0);
    float bce0_1 = softplus_fast(l1);

    s_noobj += noobj * (bce0_0 + bce0_1);
    s_m += obj;

    float c0x = sigmoid_fast(x0), c0y = sigmoid_fast(y0);
    float c0w = sigmoid_fast(w0), c0h = sigmoid_fast(h0);
    float c1x = sigmoid_fast(x1), c1y = sigmoid_fast(y1);
    float c1w = sigmoid_fast(w1), c1h = sigmoid_fast(h1);

    float tlx = tx - tw * 0.5f, tly = ty - th * 0.5f;
    float trx = tx + tw * 0.5f, trY = ty + th * 0.5f;
    float area_t = tw * th;

    float wx0 = fmaxf(0.0f, fminf(c0x + c0w * 0.5f, trx) - fmaxf(c0x - c0w * 0.5f, tlx));
    float wy0 = fmaxf(0.0f, fminf(c0y + c0h * 0.5f, trY) - fmaxf(c0y - c0h * 0.5f, tly));
    float inter0 = wx0 * wy0;
    float den0 = c0w * c0h + area_t - inter0 + 1e-10f;

    float wx1 = fmaxf(0.0f, fminf(c1x + c1w * 0.5f, trx) - fmaxf(c1x - c1w * 0.5f, tlx));
    float wy1 = fmaxf(0.0f, fminf(c1y + c1h * 0.5f, trY) - fmaxf(c1y - c1h * 0.5f, tly));
    float inter1 = wx1 * wy1;
    float den1 = c1w * c1h + area_t - inter1 + 1e-10f;

    // argmax(iou): box1 wins iff strictly greater (first-max tie-break);
    // denominators > 0, so compare cross-products (no division).
    bool r1 = inter1 * den0 > inter0 * den1;

    float rx = r1 ? c1x : c0x, ry = r1 ? c1y : c0y;
    float rw = r1 ? c1w : c0w, rh = r1 ? c1h : c0h;
    float rl = r1 ? l1 : l0;
    float rb = r1 ? bce0_1 : bce0_0;
    float nb = r1 ? bce0_0 : bce0_1;

    float dx = rx - tx, dy = ry - ty, dw = rw - tw, dh = rh - th;
    s_xy    += obj * (dx * dx + dy * dy);
    s_wh    += obj * (dw * dw + dh * dh);
    s_obj   += obj * (rb - rl);   // bce1 of responsible box
    s_nresp += obj * nb;          // bce0 of non-responsible box
}

__device__ __forceinline__ void process_pair(
    const float4& i0, const float4& i1, const float4& i2,
    const float4& i3, const float4& i4,
    const float2& t0, const float2& t1, const float2& t2,
    const float2& t3, const float2& t4,
    float& s_noobj, float& s_xy, float& s_wh,
    float& s_obj, float& s_nresp, float& s_m)
{
    process_cell(i0.x, i0.y, i0.z, i0.w, i1.x,
                 i1.y, i1.z, i1.w, i2.x, i2.y,
                 t0.x, t0.y, t1.x, t1.y, t2.x,
                 s_noobj, s_xy, s_wh, s_obj, s_nresp, s_m);
    process_cell(i2.z, i2.w, i3.x, i3.y, i3.z,
                 i3.w, i4.x, i4.y, i4.z, i4.w,
                 t2.y, t3.x, t3.y, t4.x, t4.y,
                 s_noobj, s_xy, s_wh, s_obj, s_nresp, s_m);
}

__global__ void __launch_bounds__(THREADS, 4)   // 128-reg budget: keep loads live
yolo_fused_kernel(const float4* __restrict__ inp4, const float2* __restrict__ tgt2,
                  float* __restrict__ out) {
    // two pair-groups per thread, both coalesced across the block
    int ta = blockIdx.x * (THREADS * 2) + threadIdx.x;
    int tb = ta + THREADS;

    // ---- front-batched loads: 10x LDG.128 + 10x LDG.64 per thread ----
    const float4* ipA = inp4 + (size_t)ta * 5;
    const float4* ipB = inp4 + (size_t)tb * 5;
    float4 a0 = ipA[0], a1 = ipA[1], a2 = ipA[2], a3 = ipA[3], a4 = ipA[4];
    float4 b0 = ipB[0], b1 = ipB[1], b2 = ipB[2], b3 = ipB[3], b4 = ipB[4];
    const float2* tpA = tgt2 + (size_t)ta * 5;
    const float2* tpB = tgt2 + (size_t)tb * 5;
    float2 u0 = tpA[0], u1 = tpA[1], u2 = tpA[2], u3 = tpA[3], u4 = tpA[4];
    float2 v0 = tpB[0], v1 = tpB[1], v2 = tpB[2], v3 = tpB[3], v4 = tpB[4];

    float s_noobj = 0.0f, s_xy = 0.0f, s_wh = 0.0f;
    float s_obj = 0.0f, s_nresp = 0.0f, s_m = 0.0f;

    process_pair(a0, a1, a2, a3, a4, u0, u1, u2, u3, u4,
                 s_noobj, s_xy, s_wh, s_obj, s_nresp, s_m);
    process_pair(b0, b1, b2, b3, b4, v0, v1, v2, v3, v4,
                 s_noobj, s_xy, s_wh, s_obj, s_nresp, s_m);

    // ---- warp + block reduction ----
    float v[6] = {s_noobj, s_xy, s_wh, s_obj, s_nresp, s_m};
#pragma unroll
    for (int k = 0; k < 6; k++) {
#pragma unroll
        for (int off = 16; off > 0; off >>= 1)
            v[k] += __shfl_xor_sync(0xffffffffu, v[k], off);
    }

    __shared__ float sh[NWARPS][6];
    __shared__ bool is_last;
    int lane = threadIdx.x & 31;
    int warp = threadIdx.x >> 5;
    if (lane == 0) {
#pragma unroll
        for (int k = 0; k < 6; k++) sh[warp][k] = v[k];
    }
    __syncthreads();

    if (warp == 0) {
        float w[6];
#pragma unroll
        for (int k = 0; k < 6; k++)
            w[k] = (lane < NWARPS) ? sh[lane][k] : 0.0f;
#pragma unroll
        for (int k = 0; k < 6; k++) {
#pragma unroll
            for (int off = NWARPS / 2; off > 0; off >>= 1)
                w[k] += __shfl_xor_sync(0xffffffffu, w[k], off);
        }
        if (lane == 0) {
#pragma unroll
            for (int k = 0; k < 6; k++) atomicAdd(&g_acc[k], w[k]);
            __threadfence();
            unsigned int old = atomicAdd(&g_count, 1u);
            is_last = (old == (unsigned int)(gridDim.x - 1));
        }
    }
    __syncthreads();

    // ---- last block finalizes + resets for the next graph replay ----
    if (is_last && threadIdx.x == 0) {
        volatile float* ga = g_acc;
        float a_noobj = ga[0], a_xy = ga[1], a_wh = ga[2];
        float a_obj = ga[3], a_nresp = ga[4], m = ga[5];
        float n_noobj = (float)NCELLS - m;
        float loss_noobj = a_noobj / (n_noobj * 2.0f) + a_nresp / m;  // B=2
        float loss_xy = a_xy / (m * 2.0f);
        float loss_wh = a_wh / (m * 2.0f);
        float loss_obj = a_obj / m;
        out[0] = loss_noobj + loss_xy + loss_wh + loss_obj;
        out[1] = loss_noobj;
        out[2] = loss_xy;
        out[3] = loss_wh;
        out[4] = loss_obj;
#pragma unroll
        for (int k = 0; k < 6; k++) g_acc[k] = 0.0f;
        g_count = 0u;
    }
}

extern "C" void kernel_launch(void* const* d_in, const int* in_sizes, int n_in,
                              void* d_out, int out_size) {
    const float4* inp4 = (const float4*)d_in[0];
    const float2* tgt2 = (const float2*)d_in[1];
    float* out = (float*)d_out;
    yolo_fused_kernel<<<BLOCKS, THREADS>>>(inp4, tgt2, out);
}

// round 6
// speedup vs baseline: 1.0023x; 1.0023x over previous
#include <cuda_runtime.h>
#include <cuda_bf16.h>
#include <cstdint>

// YOLO loss: N=64, S=128, B=2.
// input (N,S,S,10) fp32, target (N,S,S,5) fp32 -> 5 fp32 scalars.
// Coalesced cp.async tile staging into smem (kills the 80B-stride L1tex
// wavefront amplification), then per-cell processing from smem.

#define NCELLS (64 * 128 * 128)
#define THREADS 128
#define NWARPS (THREADS / 32)
#define TILE 512                       // cells per block
#define BLOCKS (NCELLS / TILE)         // 2048
#define CELLS_PER_THREAD (TILE / THREADS)  // 4

__device__ float g_acc[6];   // 0:S_noobj 1:S_xy 2:S_wh 3:S_obj 4:S_nresp 5:m
__device__ unsigned int g_count;

__device__ __forceinline__ float softplus_fast(float x) {
    return fmaxf(x, 0.0f) + __logf(1.0f + __expf(-fabsf(x)));
}
__device__ __forceinline__ float sigmoid_fast(float x) {
    return __fdividef(1.0f, 1.0f + __expf(-x));
}

__device__ __forceinline__ void cp_async16(unsigned int smem_addr, const void* gptr) {
    asm volatile("cp.async.cg.shared.global [%0], [%1], 16;"
                 :: "r"(smem_addr), "l"(gptr) : "memory");
}

// Branchless single-cell processing.
__device__ __forceinline__ void process_cell(
    float l0, float x0, float y0, float w0, float h0,
    float l1, float x1, float y1, float w1, float h1,
    float tconf, float tx, float ty, float tw, float th,
    float& s_noobj, float& s_xy, float& s_wh,
    float& s_obj, float& s_nresp, float& s_m)
{
    float obj = (tconf > 0.0f) ? 1.0f : 0.0f;
    float noobj = 1.0f - obj;

    float bce0_0 = softplus_fast(l0);
    float bce0_1 = softplus_fast(l1);

    s_noobj += noobj * (bce0_0 + bce0_1);
    s_m += obj;

    float c0x = sigmoid_fast(x0), c0y = sigmoid_fast(y0);
    float c0w = sigmoid_fast(w0), c0h = sigmoid_fast(h0);
    float c1x = sigmoid_fast(x1), c1y = sigmoid_fast(y1);
    float c1w = sigmoid_fast(w1), c1h = sigmoid_fast(h1);

    float tlx = tx - tw * 0.5f, tly = ty - th * 0.5f;
    float trx = tx + tw * 0.5f, trY = ty + th * 0.5f;
    float area_t = tw * th;

    float wx0 = fmaxf(0.0f, fminf(c0x + c0w * 0.5f, trx) - fmaxf(c0x - c0w * 0.5f, tlx));
    float wy0 = fmaxf(0.0f, fminf(c0y + c0h * 0.5f, trY) - fmaxf(c0y - c0h * 0.5f, tly));
    float inter0 = wx0 * wy0;
    float den0 = c0w * c0h + area_t - inter0 + 1e-10f;

    float wx1 = fmaxf(0.0f, fminf(c1x + c1w * 0.5f, trx) - fmaxf(c1x - c1w * 0.5f, tlx));
    float wy1 = fmaxf(0.0f, fminf(c1y + c1h * 0.5f, trY) - fmaxf(c1y - c1h * 0.5f, tly));
    float inter1 = wx1 * wy1;
    float den1 = c1w * c1h + area_t - inter1 + 1e-10f;

    // argmax(iou): box1 wins iff strictly greater (first-max tie-break);
    // denominators > 0 -> cross-product compare, no division.
    bool r1 = inter1 * den0 > inter0 * den1;

    float rx = r1 ? c1x : c0x, ry = r1 ? c1y : c0y;
    float rw = r1 ? c1w : c0w, rh = r1 ? c1h : c0h;
    float rl = r1 ? l1 : l0;
    float rb = r1 ? bce0_1 : bce0_0;
    float nb = r1 ? bce0_0 : bce0_1;

    float dx = rx - tx, dy = ry - ty, dw = rw - tw, dh = rh - th;
    s_xy    += obj * (dx * dx + dy * dy);
    s_wh    += obj * (dw * dw + dh * dh);
    s_obj   += obj * (rb - rl);
    s_nresp += obj * nb;
}

__global__ void __launch_bounds__(THREADS)
yolo_fused_kernel(const float* __restrict__ inp, const float* __restrict__ tgt,
                  float* __restrict__ out) {
    __shared__ float s_in[TILE * 10];   // 20 KB
    __shared__ float s_tg[TILE * 5];    // 10 KB

    int tid = threadIdx.x;
    size_t cell0 = (size_t)blockIdx.x * TILE;

    // ---- Phase 1: coalesced 16B cp.async staging ----
    {
        unsigned int s_in_addr = (unsigned int)__cvta_generic_to_shared(s_in);
        unsigned int s_tg_addr = (unsigned int)__cvta_generic_to_shared(s_tg);
        const float* gin = inp + cell0 * 10;   // 20480 B, 16B-aligned
        const float* gtg = tgt + cell0 * 5;    // 10240 B, 16B-aligned
        // input: 1280 float4 -> 10 per thread
#pragma unroll
        for (int k = 0; k < 10; k++) {
            int idx = tid + k * THREADS;       // float4 index
            cp_async16(s_in_addr + idx * 16, gin + idx * 4);
        }
        // target: 640 float4 -> 5 per thread
#pragma unroll
        for (int k = 0; k < 5; k++) {
            int idx = tid + k * THREADS;
            cp_async16(s_tg_addr + idx * 16, gtg + idx * 4);
        }
        asm volatile("cp.async.commit_group;" ::: "memory");
        asm volatile("cp.async.wait_group 0;" ::: "memory");
    }
    __syncthreads();

    // ---- Phase 2: process 4 cells/thread from smem ----
    float s_noobj = 0.0f, s_xy = 0.0f, s_wh = 0.0f;
    float s_obj = 0.0f, s_nresp = 0.0f, s_m = 0.0f;

#pragma unroll
    for (int k = 0; k < CELLS_PER_THREAD; k++) {
        int c = tid + k * THREADS;
        // input: 10 floats, 40B stride -> 8B aligned float2 reads
        const float2* ip = reinterpret_cast<const float2*>(s_in + c * 10);
        float2 a0 = ip[0], a1 = ip[1], a2 = ip[2], a3 = ip[3], a4 = ip[4];
        // target: 5 floats, scalar reads (stride 5 -> conflict-free banks)
        const float* tp = s_tg + c * 5;
        float tconf = tp[0], tx = tp[1], ty = tp[2], tw = tp[3], th = tp[4];

        process_cell(a0.x, a0.y, a1.x, a1.y, a2.x,
                     a2.y, a3.x, a3.y, a4.x, a4.y,
                     tconf, tx, ty, tw, th,
                     s_noobj, s_xy, s_wh, s_obj, s_nresp, s_m);
    }

    // ---- warp + block reduction ----
    float v[6] = {s_noobj, s_xy, s_wh, s_obj, s_nresp, s_m};
#pragma unroll
    for (int k = 0; k < 6; k++) {
#pragma unroll
        for (int off = 16; off > 0; off >>= 1)
            v[k] += __shfl_xor_sync(0xffffffffu, v[k], off);
    }

    __shared__ float sh[NWARPS][6];
    __shared__ bool is_last;
    int lane = tid & 31;
    int warp = tid >> 5;
    if (lane == 0) {
#pragma unroll
        for (int k = 0; k < 6; k++) sh[warp][k] = v[k];
    }
    __syncthreads();

    if (warp == 0) {
        float w[6];
#pragma unroll
        for (int k = 0; k < 6; k++)
            w[k] = (lane < NWARPS) ? sh[lane][k] : 0.0f;
#pragma unroll
        for (int k = 0; k < 6; k++) {
#pragma unroll
            for (int off = NWARPS / 2; off > 0; off >>= 1)
                w[k] += __shfl_xor_sync(0xffffffffu, w[k], off);
        }
        if (lane == 0) {
#pragma unroll
            for (int k = 0; k < 6; k++) atomicAdd(&g_acc[k], w[k]);
            __threadfence();
            unsigned int old = atomicAdd(&g_count, 1u);
            is_last = (old == (unsigned int)(gridDim.x - 1));
        }
    }
    __syncthreads();

    // ---- last block finalizes + resets for the next graph replay ----
    if (is_last && tid == 0) {
        volatile float* ga = g_acc;
        float a_noobj = ga[0], a_xy = ga[1], a_wh = ga[2];
        float a_obj = ga[3], a_nresp = ga[4], m = ga[5];
        float n_noobj = (float)NCELLS - m;
        float loss_noobj = a_noobj / (n_noobj * 2.0f) + a_nresp / m;  // B=2
        float loss_xy = a_xy / (m * 2.0f);
        float loss_wh = a_wh / (m * 2.0f);
        float loss_obj = a_obj / m;
        out[0] = loss_noobj + loss_xy + loss_wh + loss_obj;
        out[1] = loss_noobj;
        out[2] = loss_xy;
        out[3] = loss_wh;
        out[4] = loss_obj;
#pragma unroll
        for (int k = 0; k < 6; k++) g_acc[k] = 0.0f;
        g_count = 0u;
    }
}

extern "C" void kernel_launch(void* const* d_in, const int* in_sizes, int n_in,
                              void* d_out, int out_size) {
    const float* inp = (const float*)d_in[0];
    const float* tgt = (const float*)d_in[1];
    float* out = (float*)d_out;
    yolo_fused_kernel<<<BLOCKS, THREADS>>>(inp, tgt, out);
}

// round 7
// speedup vs baseline: 1.6000x; 1.5963x over previous
#include <cuda_runtime.h>
#include <cuda_bf16.h>
#include <cstdint>

// YOLO loss: N=64, S=128, B=2.
// input (N,S,S,10) fp32, target (N,S,S,5) fp32 -> 5 fp32 scalars.
// 512 blocks x 256 threads, 8 cells/thread (2 groups of 4 with batched
// vector loads), smem-transpose block reduction, single-kernel finalize.

#define NCELLS (64 * 128 * 128)
#define THREADS 256
#define PAIRS_PER_BLOCK 1024           // 2048 cells per block
#define BLOCKS (NCELLS / 2 / PAIRS_PER_BLOCK)   // 512

__device__ float g_acc[6];   // 0:S_noobj 1:S_xy 2:S_wh 3:S_obj 4:S_nresp 5:m
__device__ unsigned int g_count;

__device__ __forceinline__ float softplus_fast(float x) {
    return fmaxf(x, 0.0f) + __logf(1.0f + __expf(-fabsf(x)));
}
__device__ __forceinline__ float sigmoid_fast(float x) {
    return __fdividef(1.0f, 1.0f + __expf(-x));
}

// Branchless single-cell processing.
__device__ __forceinline__ void process_cell(
    float l0, float x0, float y0, float w0, float h0,
    float l1, float x1, float y1, float w1, float h1,
    float tconf, float tx, float ty, float tw, float th,
    float& s_noobj, float& s_xy, float& s_wh,
    float& s_obj, float& s_nresp, float& s_m)
{
    float obj = (tconf > 0.0f) ? 1.0f : 0.0f;
    float noobj = 1.0f - obj;

    float bce0_0 = softplus_fast(l0);
    float bce0_1 = softplus_fast(l1);

    s_noobj += noobj * (bce0_0 + bce0_1);
    s_m += obj;

    float c0x = sigmoid_fast(x0), c0y = sigmoid_fast(y0);
    float c0w = sigmoid_fast(w0), c0h = sigmoid_fast(h0);
    float c1x = sigmoid_fast(x1), c1y = sigmoid_fast(y1);
    float c1w = sigmoid_fast(w1), c1h = sigmoid_fast(h1);

    float tlx = tx - tw * 0.5f, tly = ty - th * 0.5f;
    float trx = tx + tw * 0.5f, trY = ty + th * 0.5f;
    float area_t = tw * th;

    float wx0 = fmaxf(0.0f, fminf(c0x + c0w * 0.5f, trx) - fmaxf(c0x - c0w * 0.5f, tlx));
    float wy0 = fmaxf(0.0f, fminf(c0y + c0h * 0.5f, trY) - fmaxf(c0y - c0h * 0.5f, tly));
    float inter0 = wx0 * wy0;
    float den0 = c0w * c0h + area_t - inter0 + 1e-10f;

    float wx1 = fmaxf(0.0f, fminf(c1x + c1w * 0.5f, trx) - fmaxf(c1x - c1w * 0.5f, tlx));
    float wy1 = fmaxf(0.0f, fminf(c1y + c1h * 0.5f, trY) - fmaxf(c1y - c1h * 0.5f, tly));
    float inter1 = wx1 * wy1;
    float den1 = c1w * c1h + area_t - inter1 + 1e-10f;

    // argmax(iou): box1 wins iff strictly greater (first-max tie-break);
    // denominators > 0 -> cross-product compare, no division.
    bool r1 = inter1 * den0 > inter0 * den1;

    float rx = r1 ? c1x : c0x, ry = r1 ? c1y : c0y;
    float rw = r1 ? c1w : c0w, rh = r1 ? c1h : c0h;
    float rl = r1 ? l1 : l0;
    float rb = r1 ? bce0_1 : bce0_0;
    float nb = r1 ? bce0_0 : bce0_1;

    float dx = rx - tx, dy = ry - ty, dw = rw - tw, dh = rh - th;
    s_xy    += obj * (dx * dx + dy * dy);
    s_wh    += obj * (dw * dw + dh * dh);
    s_obj   += obj * (rb - rl);
    s_nresp += obj * nb;
}

__device__ __forceinline__ void process_pair(
    const float4& i0, const float4& i1, const float4& i2,
    const float4& i3, const float4& i4,
    const float2& t0, const float2& t1, const float2& t2,
    const float2& t3, const float2& t4,
    float& s_noobj, float& s_xy, float& s_wh,
    float& s_obj, float& s_nresp, float& s_m)
{
    process_cell(i0.x, i0.y, i0.z, i0.w, i1.x,
                 i1.y, i1.z, i1.w, i2.x, i2.y,
                 t0.x, t0.y, t1.x, t1.y, t2.x,
                 s_noobj, s_xy, s_wh, s_obj, s_nresp, s_m);
    process_cell(i2.z, i2.w, i3.x, i3.y, i3.z,
                 i3.w, i4.x, i4.y, i4.z, i4.w,
                 t2.y, t3.x, t3.y, t4.x, t4.y,
                 s_noobj, s_xy, s_wh, s_obj, s_nresp, s_m);
}

__global__ void __launch_bounds__(THREADS)
yolo_fused_kernel(const float4* __restrict__ inp4, const float2* __restrict__ tgt2,
                  float* __restrict__ out) {
    int tid = threadIdx.x;
    int base = blockIdx.x * PAIRS_PER_BLOCK;

    float s_noobj = 0.0f, s_xy = 0.0f, s_wh = 0.0f;
    float s_obj = 0.0f, s_nresp = 0.0f, s_m = 0.0f;

    // ---- 8 cells/thread: 2 groups x 2 pair-groups, loads batched per group ----
#pragma unroll
    for (int g = 0; g < 2; g++) {
        int ta = base + g * (THREADS * 2) + tid;
        int tb = ta + THREADS;

        const float4* ipA = inp4 + (size_t)ta * 5;
        const float4* ipB = inp4 + (size_t)tb * 5;
        float4 a0 = ipA[0], a1 = ipA[1], a2 = ipA[2], a3 = ipA[3], a4 = ipA[4];
        float4 b0 = ipB[0], b1 = ipB[1], b2 = ipB[2], b3 = ipB[3], b4 = ipB[4];
        const float2* tpA = tgt2 + (size_t)ta * 5;
        const float2* tpB = tgt2 + (size_t)tb * 5;
        float2 u0 = tpA[0], u1 = tpA[1], u2 = tpA[2], u3 = tpA[3], u4 = tpA[4];
        float2 v0 = tpB[0], v1 = tpB[1], v2 = tpB[2], v3 = tpB[3], v4 = tpB[4];

        process_pair(a0, a1, a2, a3, a4, u0, u1, u2, u3, u4,
                     s_noobj, s_xy, s_wh, s_obj, s_nresp, s_m);
        process_pair(b0, b1, b2, b3, b4, v0, v1, v2, v3, v4,
                     s_noobj, s_xy, s_wh, s_obj, s_nresp, s_m);
    }

    // ---- block reduction via smem transpose: 6 STS/thread, then 6 warps
    //      each reduce one 256-float array (8 LDS + shuffle + 1 atomic) ----
    __shared__ float sh[6][THREADS];
    sh[0][tid] = s_noobj;
    sh[1][tid] = s_xy;
    sh[2][tid] = s_wh;
    sh[3][tid] = s_obj;
    sh[4][tid] = s_nresp;
    sh[5][tid] = s_m;
    __syncthreads();

    int lane = tid & 31;
    int warp = tid >> 5;
    if (warp < 6) {
        float v = 0.0f;
#pragma unroll
        for (int j = 0; j < THREADS / 32; j++)
            v += sh[warp][lane + j * 32];
#pragma unroll
        for (int off = 16; off > 0; off >>= 1)
            v += __shfl_xor_sync(0xffffffffu, v, off);
        if (lane == 0)
            atomicAdd(&g_acc[warp], v);
    }
    __syncthreads();

    // ---- last block finalizes + resets for the next graph replay ----
    if (tid == 0) {
        __threadfence();
        unsigned int old = atomicAdd(&g_count, 1u);
        if (old == (unsigned int)(gridDim.x - 1)) {
            volatile float* ga = g_acc;
            float a_noobj = ga[0], a_xy = ga[1], a_wh = ga[2];
            float a_obj = ga[3], a_nresp = ga[4], m = ga[5];
            float n_noobj = (float)NCELLS - m;
            float loss_noobj = a_noobj / (n_noobj * 2.0f) + a_nresp / m;  // B=2
            float loss_xy = a_xy / (m * 2.0f);
            float loss_wh = a_wh / (m * 2.0f);
            float loss_obj = a_obj / m;
            out[0] = loss_noobj + loss_xy + loss_wh + loss_obj;
            out[1] = loss_noobj;
            out[2] = loss_xy;
            out[3] = loss_wh;
            out[4] = loss_obj;
#pragma unroll
            for (int k = 0; k < 6; k++) g_acc[k] = 0.0f;
            g_count = 0u;
        }
    }
}

extern "C" void kernel_launch(void* const* d_in, const int* in_sizes, int n_in,
                              void* d_out, int out_size) {
    const float4* inp4 = (const float4*)d_in[0];
    const float2* tgt2 = (const float2*)d_in[1];
    float* out = (float*)d_out;
    yolo_fused_kernel<<<BLOCKS, THREADS>>>(inp4, tgt2, out);
}